// round 4
// baseline (speedup 1.0000x reference)
#include <cuda_runtime.h>
#include <cstdint>

#define NG   262144          // graphs
#define NPG  6               // nodes per graph
#define NN   (NG*NPG)        // nodes
#define FD   13              // input features
#define HD   32              // hidden
#define GD   9               // global features
#define EPG  30              // directed edges per graph
#define BNEPS 1e-5f

// ---------------- scratch ----------------
__device__ float g_h1[(size_t)NN * HD];   // 201 MB
__device__ float g_h2[(size_t)NN * HD];   // 201 MB
__device__ float g_sum1[HD], g_sq1[HD], g_sum2[HD], g_sq2[HD];
__device__ float g_scale1[HD], g_shift1[HD], g_scale2[HD], g_shift2[HD];

__global__ void k_zero_stats() {
    int i = threadIdx.x;
    if (i < HD) { g_sum1[i] = 0.f; g_sq1[i] = 0.f; g_sum2[i] = 0.f; g_sq2[i] = 0.f; }
}

// lane t<6 computes deg[t] = 1 + sum of incoming weights; all lanes get dv[s]=rsqrt(deg[s]).
__device__ __forceinline__ void dinv6(float we, int lane, float dv[6]) {
    float d = 1.0f;
    int t = lane;
    #pragma unroll
    for (int s = 0; s < 6; s++) {
        int idx = (s * 5 + (t < s ? t : t - 1)) & 31;
        float w = __shfl_sync(0xffffffffu, we, idx);
        if (t < 6 && s != t) d += w;
    }
    float dvt = (t < 6) ? rsqrtf(d) : 0.f;
    #pragma unroll
    for (int s = 0; s < 6; s++) dv[s] = __shfl_sync(0xffffffffu, dvt, s);
}

// normalized adjacency into shared, row stride 8 floats (16B-aligned rows, pads zero)
__device__ __forceinline__ void buildA(float we, int lane, const float dv[6], float* sA) {
    if (lane < EPG) {
        int s = lane / 5, j = lane - s * 5, t = j + (j >= s);
        sA[t * 8 + s] = dv[t] * we * dv[s];
    }
    if (lane < 6) sA[lane * 8 + lane] = dv[lane] * dv[lane];
}

// ---------------- K1: h1_pre = (A @ x) @ W1 + b1 ; BN1 stats ----------------
__global__ void __launch_bounds__(256) k1(const float* __restrict__ x,
                                          const float* __restrict__ ew,
                                          const float* __restrict__ W1,
                                          const float* __restrict__ b1) {
    __shared__ __align__(16) float sbuf[8][240];  // per warp: sx[0..77], sA[80..127], sxa[128..223] (6x16)
    __shared__ float sred[8][64];
    const int lane = threadIdx.x & 31, w = threadIdx.x >> 5;
    float* sx  = sbuf[w];
    float* sA  = sbuf[w] + 80;
    float* sxa = sbuf[w] + 128;

    float w1c[16];
    #pragma unroll
    for (int c = 0; c < FD; c++) w1c[c] = W1[c * HD + lane];
    w1c[13] = 0.f; w1c[14] = 0.f; w1c[15] = 0.f;
    const float b1l = b1[lane];

    // zero A-row pads + sxa pads once (persist across graphs)
    if (lane < 12) sA[(lane >> 1) * 8 + 6 + (lane & 1)] = 0.f;
    if (lane < 18) sxa[(lane / 3) * 16 + 13 + (lane % 3)] = 0.f;
    __syncwarp();

    float ssum = 0.f, ssq = 0.f;
    const int warpId = (blockIdx.x * blockDim.x + threadIdx.x) >> 5;
    const int nwarps = (gridDim.x * blockDim.x) >> 5;

    for (int g = warpId; g < NG; g += nwarps) {
        float we = (lane < EPG) ? ew[(size_t)g * EPG + lane] : 0.f;
        const float* xg = x + (size_t)g * (NPG * FD);
        #pragma unroll
        for (int r = 0; r < 3; r++) { int i = lane + r * 32; if (i < NPG * FD) sx[i] = xg[i]; }

        float dv[6]; dinv6(we, lane, dv);
        buildA(we, lane, dv, sA);
        __syncwarp();

        // xa[t][c] = sum_s A[t][s] * x[s][c]
        #pragma unroll
        for (int r = 0; r < 3; r++) {
            int i = lane + r * 32;
            if (i < NPG * FD) {
                int t = i / FD, c = i - t * FD;
                float v = 0.f;
                #pragma unroll
                for (int s = 0; s < 6; s++) v = fmaf(sA[t * 8 + s], sx[s * FD + c], v);
                sxa[t * 16 + c] = v;
            }
        }
        __syncwarp();

        float* outp = g_h1 + (size_t)g * (NPG * HD) + lane;
        #pragma unroll
        for (int t = 0; t < NPG; t++) {
            float acc = b1l;
            const float4* rowp = (const float4*)(sxa + t * 16);
            #pragma unroll
            for (int cc = 0; cc < 4; cc++) {
                float4 v4 = rowp[cc];
                acc = fmaf(v4.x, w1c[4 * cc + 0], acc);
                acc = fmaf(v4.y, w1c[4 * cc + 1], acc);
                acc = fmaf(v4.z, w1c[4 * cc + 2], acc);
                acc = fmaf(v4.w, w1c[4 * cc + 3], acc);
            }
            outp[t * HD] = acc;
            ssum += acc;
            ssq = fmaf(acc, acc, ssq);
        }
        __syncwarp();
    }

    sred[w][lane] = ssum; sred[w][32 + lane] = ssq;
    __syncthreads();
    if (threadIdx.x < 64) {
        float tot = 0.f;
        #pragma unroll
        for (int i = 0; i < 8; i++) tot += sred[i][threadIdx.x];
        if (threadIdx.x < 32) atomicAdd(&g_sum1[threadIdx.x], tot);
        else                  atomicAdd(&g_sq1[threadIdx.x - 32], tot);
    }
}

// ---------------- finalize BN params ----------------
__global__ void k_bn(const float* __restrict__ gam, const float* __restrict__ bet, int which) {
    int f = threadIdx.x;
    if (f < HD) {
        float n = (float)NN;
        float s  = which ? g_sum2[f] : g_sum1[f];
        float sq = which ? g_sq2[f]  : g_sq1[f];
        float mean = s / n;
        float var = sq / n - mean * mean;
        if (var < 0.f) var = 0.f;
        float sc = gam[f] * rsqrtf(var + BNEPS);
        float sh = bet[f] - mean * sc;
        if (which) { g_scale2[f] = sc; g_shift2[f] = sh; }
        else       { g_scale1[f] = sc; g_shift1[f] = sh; }
    }
}

// ---------------- K3: h1=relu(bn1(h1_pre)); h2_pre=(A@h1)@W2+b2 ; BN2 stats ----------------
__global__ void __launch_bounds__(256) k3(const float* __restrict__ ew,
                                          const float* __restrict__ W2,
                                          const float* __restrict__ b2) {
    __shared__ __align__(16) float sbuf[8][240];  // per warp: sA[0..47], sha[48..239]
    __shared__ float sred[8][64];
    const int lane = threadIdx.x & 31, w = threadIdx.x >> 5;
    float* sA  = sbuf[w];
    float* sha = sbuf[w] + 48;

    float w2c[HD];
    #pragma unroll
    for (int c = 0; c < HD; c++) w2c[c] = W2[c * HD + lane];
    const float b2l = b2[lane];
    const float s1 = g_scale1[lane], f1 = g_shift1[lane];

    if (lane < 12) sA[(lane >> 1) * 8 + 6 + (lane & 1)] = 0.f;  // zero A pads once
    __syncwarp();

    float ssum = 0.f, ssq = 0.f;
    const int warpId = (blockIdx.x * blockDim.x + threadIdx.x) >> 5;
    const int nwarps = (gridDim.x * blockDim.x) >> 5;

    for (int g = warpId; g < NG; g += nwarps) {
        // issue global loads first so they overlap the shuffle chain
        const float* hp = g_h1 + (size_t)g * (NPG * HD) + lane;
        float hraw[NPG];
        #pragma unroll
        for (int t = 0; t < NPG; t++) hraw[t] = hp[t * HD];
        float we = (lane < EPG) ? ew[(size_t)g * EPG + lane] : 0.f;

        float dv[6]; dinv6(we, lane, dv);
        buildA(we, lane, dv, sA);

        float h[NPG];
        #pragma unroll
        for (int t = 0; t < NPG; t++) h[t] = fmaxf(0.f, fmaf(hraw[t], s1, f1));
        __syncwarp();

        // ha[t] (this lane's feature) = sum_s A[t][s] * h[s]  (A rows via float4 broadcast)
        #pragma unroll
        for (int t = 0; t < NPG; t++) {
            const float4* arow = (const float4*)(sA + t * 8);
            float4 a0 = arow[0], a1 = arow[1];
            float v;
            v = a0.x * h[0];
            v = fmaf(a0.y, h[1], v);
            v = fmaf(a0.z, h[2], v);
            v = fmaf(a0.w, h[3], v);
            v = fmaf(a1.x, h[4], v);
            v = fmaf(a1.y, h[5], v);
            sha[t * HD + lane] = v;
        }
        __syncwarp();

        float* outp = g_h2 + (size_t)g * (NPG * HD) + lane;
        #pragma unroll
        for (int t = 0; t < NPG; t++) {
            float acc = b2l;
            const float4* rowp = (const float4*)(sha + t * HD);
            #pragma unroll
            for (int cc = 0; cc < 8; cc++) {
                float4 v4 = rowp[cc];
                acc = fmaf(v4.x, w2c[4 * cc + 0], acc);
                acc = fmaf(v4.y, w2c[4 * cc + 1], acc);
                acc = fmaf(v4.z, w2c[4 * cc + 2], acc);
                acc = fmaf(v4.w, w2c[4 * cc + 3], acc);
            }
            outp[t * HD] = acc;
            ssum += acc;
            ssq = fmaf(acc, acc, ssq);
        }
        __syncwarp();
    }

    sred[w][lane] = ssum; sred[w][32 + lane] = ssq;
    __syncthreads();
    if (threadIdx.x < 64) {
        float tot = 0.f;
        #pragma unroll
        for (int i = 0; i < 8; i++) tot += sred[i][threadIdx.x];
        if (threadIdx.x < 32) atomicAdd(&g_sum2[threadIdx.x], tot);
        else                  atomicAdd(&g_sq2[threadIdx.x - 32], tot);
    }
}

// ---------------- K5: bn2+relu, mean-pool, readout, sigmoid ----------------
__global__ void __launch_bounds__(256) k5(const float* __restrict__ gf,
                                          const float* __restrict__ Wo,
                                          const float* __restrict__ bo,
                                          const float* __restrict__ Wb,
                                          const float* __restrict__ bb,
                                          float* __restrict__ out) {
    const int lane = threadIdx.x & 31;
    const int g = (blockIdx.x * blockDim.x + threadIdx.x) >> 5;
    if (g >= NG) return;

    const float s2 = g_scale2[lane], f2 = g_shift2[lane];
    const float wol = Wo[lane], wbl = Wb[lane];
    const float wog = (lane < GD) ? Wo[HD + lane] : 0.f;
    const float wbg = (lane < GD) ? Wb[HD + lane] : 0.f;

    const float* hp = g_h2 + (size_t)g * (NPG * HD) + lane;
    float p = 0.f;
    #pragma unroll
    for (int t = 0; t < NPG; t++) p += fmaxf(0.f, fmaf(hp[t * HD], s2, f2));
    p *= (1.0f / 6.0f);

    float gv = (lane < GD) ? gf[(size_t)g * GD + lane] : 0.f;
    float zo = fmaf(p, wol, gv * wog);
    float zb = fmaf(p, wbl, gv * wbg);
    #pragma unroll
    for (int o = 16; o; o >>= 1) {
        zo += __shfl_xor_sync(0xffffffffu, zo, o);
        zb += __shfl_xor_sync(0xffffffffu, zb, o);
    }
    if (lane == 0) {
        out[g]      = 1.0f / (1.0f + __expf(-(zo + bo[0])));
        out[NG + g] = 1.0f / (1.0f + __expf(-(zb + bb[0])));
    }
}

// ---------------- launch ----------------
extern "C" void kernel_launch(void* const* d_in, const int* in_sizes, int n_in,
                              void* d_out, int out_size) {
    const float* x   = (const float*)d_in[0];
    const float* ew  = (const float*)d_in[2];
    const float* gf  = (const float*)d_in[4];
    const float* W1  = (const float*)d_in[5];
    const float* b1  = (const float*)d_in[6];
    const float* g1  = (const float*)d_in[7];
    const float* be1 = (const float*)d_in[8];
    const float* W2  = (const float*)d_in[9];
    const float* b2  = (const float*)d_in[10];
    const float* g2  = (const float*)d_in[11];
    const float* be2 = (const float*)d_in[12];
    const float* Wo  = (const float*)d_in[13];
    const float* bo  = (const float*)d_in[14];
    const float* Wb  = (const float*)d_in[15];
    const float* bb  = (const float*)d_in[16];
    float* out = (float*)d_out;

    k_zero_stats<<<1, 64>>>();
    k1<<<2048, 256>>>(x, ew, W1, b1);
    k_bn<<<1, 32>>>(g1, be1, 0);
    k3<<<2048, 256>>>(ew, W2, b2);
    k_bn<<<1, 32>>>(g2, be2, 1);
    k5<<<NG / 8, 256>>>(gf, Wo, bo, Wb, bb, out);
}